// round 4
// baseline (speedup 1.0000x reference)
#include <cuda_runtime.h>

#define NB   256   // threads per block == rows per block
#define NBLK 256   // 256*256 = 65536 rows
#define ALPHA 0.01f

typedef unsigned long long u64;

// ---- shared memory layout (float offsets, 16B-aligned where needed) ----
#define S_WIN   0        // 3 * 8*64 = 1536
#define S_BIN   1536     // 3 * 64   = 192
#define S_WA1   1728     // 64
#define S_WA2   1792     // 64
#define S_WO1   1856     // 10*32 = 320
#define S_BO1   2176     // 32
#define S_WO2   2208     // 32*16 = 512
#define S_BO2   2720     // 16
#define S_WO3   2736     // 16
#define S_BO3   2752     // 1 (+3 pad)
#define S_WFC1  2756     // 90*64 = 5760
#define S_BFC1  8516     // 64
#define S_WG    8580     // interleaved {w_ih, w_hh}: 2*12288 = 24576
#define S_GB    33156    // per-j gru bias quad {br, bz, bni, bnh}: 64*4 = 256
#define S_WFC2  33412    // 64*5 = 320
#define S_BFC2  33732    // 5 (+3 pad)
#define S_OBS   33740    // 256*85 = 21760; later reused as per-row scr (stride 65)
#define S_TOT   (33740 + 21760)   // 55500 floats = 222000 bytes

__device__ __forceinline__ float lrelu(float v) { return fmaxf(v, ALPHA * v); }
__device__ __forceinline__ float fsig(float v)  { return __fdividef(1.0f, 1.0f + __expf(-v)); }
__device__ __forceinline__ float ftanh(float v) { return 1.0f - __fdividef(2.0f, __expf(2.0f * v) + 1.0f); }

__device__ __forceinline__ u64 pack2(float lo, float hi) {
    u64 r; asm("mov.b64 %0, {%1, %2};" : "=l"(r) : "f"(lo), "f"(hi)); return r;
}
__device__ __forceinline__ void unpack2(u64 v, float& lo, float& hi) {
    asm("mov.b64 {%0, %1}, %2;" : "=f"(lo), "=f"(hi) : "l"(v));
}
__device__ __forceinline__ u64 fma2(u64 a, u64 b, u64 c) {
    u64 d; asm("fma.rn.f32x2 %0, %1, %2, %3;" : "=l"(d) : "l"(a), "l"(b), "l"(c)); return d;
}
__device__ __forceinline__ u64 add2(u64 a, u64 b) {
    u64 d; asm("add.rn.f32x2 %0, %1, %2;" : "=l"(d) : "l"(a), "l"(b)); return d;
}

__global__ void __launch_bounds__(NB, 1)
atom_rnn_kernel(const float* __restrict__ g_obs, const float* __restrict__ g_hid,
                const float* __restrict__ w_in0, const float* __restrict__ b_in0,
                const float* __restrict__ w_in1, const float* __restrict__ b_in1,
                const float* __restrict__ w_in2, const float* __restrict__ b_in2,
                const float* __restrict__ g_W,  const float* __restrict__ g_a,
                const float* __restrict__ w_o1, const float* __restrict__ b_o1,
                const float* __restrict__ w_o2, const float* __restrict__ b_o2,
                const float* __restrict__ w_o3, const float* __restrict__ b_o3,
                const float* __restrict__ w_fc1, const float* __restrict__ b_fc1,
                const float* __restrict__ w_ih, const float* __restrict__ w_hh,
                const float* __restrict__ b_ih, const float* __restrict__ b_hh,
                const float* __restrict__ w_fc2, const float* __restrict__ b_fc2,
                float* __restrict__ out_q, float* __restrict__ out_h)
{
    extern __shared__ float sm[];
    const int tid = threadIdx.x;

    // ---------------- stage weights into shared ----------------
    #define CPY4(off, src, n) { const float4* s4_ = (const float4*)(src); \
                                float4* d4_ = (float4*)&sm[off]; \
                                for (int i = tid; i < (n)/4; i += NB) d4_[i] = s4_[i]; }
    CPY4(S_WIN,        w_in0, 512);
    CPY4(S_WIN + 512,  w_in1, 512);
    CPY4(S_WIN + 1024, w_in2, 512);
    CPY4(S_BIN,        b_in0, 64);
    CPY4(S_BIN + 64,   b_in1, 64);
    CPY4(S_BIN + 128,  b_in2, 64);
    CPY4(S_WO1, w_o1, 320);  CPY4(S_BO1, b_o1, 32);
    CPY4(S_WO2, w_o2, 512);  CPY4(S_BO2, b_o2, 16);
    CPY4(S_WO3, w_o3, 16);
    CPY4(S_WFC1, w_fc1, 5760); CPY4(S_BFC1, b_fc1, 64);
    CPY4(S_WFC2, w_fc2, 320);
    #undef CPY4
    // GRU weights interleaved: sm[S_WG + 2i] = w_ih[i], sm[S_WG + 2i+1] = w_hh[i]
    for (int i = tid; i < 12288; i += NB) {
        sm[S_WG + 2*i]     = w_ih[i];
        sm[S_WG + 2*i + 1] = w_hh[i];
    }
    // GRU biases: {b_ih[r]+b_hh[r], b_ih[z]+b_hh[z], b_ih[n], b_hh[n]} per j
    if (tid < 64) {
        const int j = tid;
        sm[S_GB + 4*j]     = b_ih[j]       + b_hh[j];
        sm[S_GB + 4*j + 1] = b_ih[64 + j]  + b_hh[64 + j];
        sm[S_GB + 4*j + 2] = b_ih[128 + j];
        sm[S_GB + 4*j + 3] = b_hh[128 + j];
    }
    if (tid == 64) sm[S_BO3] = b_o3[0];
    if (tid >= 96 && tid < 101) sm[S_BFC2 + tid - 96] = b_fc2[tid - 96];

    // Wa1 = W @ a[:64], Wa2 = W @ a[64:]
    if (tid < 128) {
        const int j = tid & 63;
        const float* av = g_a + ((tid < 64) ? 0 : 64);
        const float* wr = g_W + j * 64;
        float s = 0.f;
        #pragma unroll 8
        for (int m = 0; m < 64; ++m) s = fmaf(wr[m], av[m], s);
        sm[((tid < 64) ? S_WA1 : S_WA2) + j] = s;
    }

    // stage obs tile
    {
        const float4* src4 = (const float4*)(g_obs + (size_t)blockIdx.x * NB * 85);
        float4* dst4 = (float4*)&sm[S_OBS];
        for (int i = tid; i < NB * 85 / 4; i += NB) dst4[i] = src4[i];
    }
    __syncthreads();

    const int row = blockIdx.x * NB + tid;
    const float* orow = &sm[S_OBS + tid * 85];   // stride 85: conflict-free

    // ---------------- stage 1: tokens -> wh1/wh2 ----------------
    float wh1[10], wh2[10];
    #pragma unroll
    for (int t = 0; t < 10; ++t) {
        float o[8];
        #pragma unroll
        for (int f = 0; f < 8; ++f) o[f] = orow[(t * 8 + f + 4) % 80];
        const int sel = (t < 5) ? 0 : ((t < 9) ? 1 : 2);
        const float4* w4   = (const float4*)&sm[S_WIN + sel * 512];
        const float4* b4   = (const float4*)&sm[S_BIN + sel * 64];
        const float4* wa14 = (const float4*)&sm[S_WA1];
        const float4* wa24 = (const float4*)&sm[S_WA2];
        float s1 = 0.f, s2 = 0.f;
        #pragma unroll 4
        for (int jv = 0; jv < 16; ++jv) {
            float4 acc = b4[jv];
            #pragma unroll
            for (int f = 0; f < 8; ++f) {
                float4 wv = w4[f * 16 + jv];
                acc.x = fmaf(o[f], wv.x, acc.x);
                acc.y = fmaf(o[f], wv.y, acc.y);
                acc.z = fmaf(o[f], wv.z, acc.z);
                acc.w = fmaf(o[f], wv.w, acc.w);
            }
            acc.x = lrelu(acc.x); acc.y = lrelu(acc.y);
            acc.z = lrelu(acc.z); acc.w = lrelu(acc.w);
            float4 a1 = wa14[jv], a2 = wa24[jv];
            s1 = fmaf(acc.x, a1.x, s1); s1 = fmaf(acc.y, a1.y, s1);
            s1 = fmaf(acc.z, a1.z, s1); s1 = fmaf(acc.w, a1.w, s1);
            s2 = fmaf(acc.x, a2.x, s2); s2 = fmaf(acc.y, a2.y, s2);
            s2 = fmaf(acc.z, a2.z, s2); s2 = fmaf(acc.w, a2.w, s2);
        }
        wh1[t] = s1; wh2[t] = s2;
    }

    // ---------------- stage 2: attention + head ----------------
    float mx1[5], dinv1[5];
    #pragma unroll
    for (int c = 0; c < 5; ++c) {
        float mx = -1e30f;
        #pragma unroll
        for (int r2 = 0; r2 < 5; ++r2) mx = fmaxf(mx, lrelu(wh1[5 + c] + wh2[r2]));
        float d = 0.f;
        #pragma unroll
        for (int r2 = 0; r2 < 5; ++r2) d += __expf(lrelu(wh1[5 + c] + wh2[r2]) - mx);
        mx1[c] = mx; dinv1[c] = __fdividef(1.0f, d);
    }

    float hpv0, hpv1, hpv2, hpv3, hpv4;
    #pragma unroll 1
    for (int r = 0; r < 5; ++r) {
        const float w1r = (r == 0) ? wh1[0] : (r == 1) ? wh1[1] : (r == 2) ? wh1[2] : (r == 3) ? wh1[3] : wh1[4];
        const float w2r = (r == 0) ? wh2[0] : (r == 1) ? wh2[1] : (r == 2) ? wh2[2] : (r == 3) ? wh2[3] : wh2[4];
        float att[10];
        {
            float ev[5]; float mx = -1e30f;
            #pragma unroll
            for (int c = 0; c < 5; ++c) {
                float v = lrelu(w1r + wh2[5 + c]);
                ev[c] = v; mx = fmaxf(mx, v);
            }
            float d = 0.f;
            #pragma unroll
            for (int c = 0; c < 5; ++c) { float e_ = __expf(ev[c] - mx); att[c] = e_; d += e_; }
            float inv = __fdividef(1.0f, d);
            #pragma unroll
            for (int c = 0; c < 5; ++c) att[c] *= inv;
            #pragma unroll
            for (int c = 0; c < 5; ++c)
                att[5 + c] = __expf(lrelu(wh1[5 + c] + w2r) - mx1[c]) * dinv1[c];
        }
        float h1[32];
        {
            const float4* wv4 = (const float4*)&sm[S_WO1];
            const float4* bv4 = (const float4*)&sm[S_BO1];
            #pragma unroll
            for (int jv = 0; jv < 8; ++jv) {
                float4 acc = bv4[jv];
                #pragma unroll
                for (int k = 0; k < 10; ++k) {
                    float4 wv = wv4[k * 8 + jv];
                    acc.x = fmaf(att[k], wv.x, acc.x);
                    acc.y = fmaf(att[k], wv.y, acc.y);
                    acc.z = fmaf(att[k], wv.z, acc.z);
                    acc.w = fmaf(att[k], wv.w, acc.w);
                }
                h1[4*jv]   = lrelu(acc.x); h1[4*jv+1] = lrelu(acc.y);
                h1[4*jv+2] = lrelu(acc.z); h1[4*jv+3] = lrelu(acc.w);
            }
        }
        float h2v[16];
        {
            const float4* wv4 = (const float4*)&sm[S_WO2];
            const float4* bv4 = (const float4*)&sm[S_BO2];
            #pragma unroll
            for (int jv = 0; jv < 4; ++jv) {
                float4 acc = bv4[jv];
                #pragma unroll
                for (int k = 0; k < 32; ++k) {
                    float4 wv = wv4[k * 4 + jv];
                    acc.x = fmaf(h1[k], wv.x, acc.x);
                    acc.y = fmaf(h1[k], wv.y, acc.y);
                    acc.z = fmaf(h1[k], wv.z, acc.z);
                    acc.w = fmaf(h1[k], wv.w, acc.w);
                }
                h2v[4*jv]   = lrelu(acc.x); h2v[4*jv+1] = lrelu(acc.y);
                h2v[4*jv+2] = lrelu(acc.z); h2v[4*jv+3] = lrelu(acc.w);
            }
        }
        float v = sm[S_BO3];
        {
            const float4* wv4 = (const float4*)&sm[S_WO3];
            #pragma unroll
            for (int kv = 0; kv < 4; ++kv) {
                float4 wv = wv4[kv];
                v = fmaf(h2v[4*kv],   wv.x, v);
                v = fmaf(h2v[4*kv+1], wv.y, v);
                v = fmaf(h2v[4*kv+2], wv.z, v);
                v = fmaf(h2v[4*kv+3], wv.w, v);
            }
        }
        v = lrelu(v);
        hpv0 = (r == 0) ? v : hpv0;
        hpv1 = (r == 1) ? v : hpv1;
        hpv2 = (r == 2) ? v : hpv2;
        hpv3 = (r == 3) ? v : hpv3;
        hpv4 = (r == 4) ? v : hpv4;
    }

    float obs_out[5];
    {
        float mx = fmaxf(fmaxf(fmaxf(hpv0, hpv1), fmaxf(hpv2, hpv3)), hpv4);
        obs_out[0] = __expf(hpv0 - mx); obs_out[1] = __expf(hpv1 - mx);
        obs_out[2] = __expf(hpv2 - mx); obs_out[3] = __expf(hpv3 - mx);
        obs_out[4] = __expf(hpv4 - mx);
        float d = obs_out[0] + obs_out[1] + obs_out[2] + obs_out[3] + obs_out[4];
        float inv = __fdividef(1.0f, d);
        #pragma unroll
        for (int r = 0; r < 5; ++r) obs_out[r] *= inv;
    }

    // load h_in (latency overlaps fc1)
    float hi_[64];
    {
        const float4* hp4 = (const float4*)(g_hid + (size_t)row * 64);
        #pragma unroll
        for (int i = 0; i < 16; ++i) {
            float4 v = hp4[i];
            hi_[4*i] = v.x; hi_[4*i+1] = v.y; hi_[4*i+2] = v.z; hi_[4*i+3] = v.w;
        }
    }

    // ---------------- stage 3: fc1 in f32x2 (j-pair accumulators) ----------------
    u64 a2[32];
    {
        const ulonglong2* b2 = (const ulonglong2*)&sm[S_BFC1];
        #pragma unroll
        for (int v = 0; v < 16; ++v) { ulonglong2 q = b2[v]; a2[2*v] = q.x; a2[2*v+1] = q.y; }
    }
    #pragma unroll 1
    for (int k = 0; k < 85; ++k) {
        const float ok = orow[k];
        const u64 ok2 = pack2(ok, ok);
        const ulonglong2* w2 = (const ulonglong2*)&sm[S_WFC1 + k * 64];
        #pragma unroll
        for (int v = 0; v < 16; ++v) {
            ulonglong2 q = w2[v];
            a2[2*v]   = fma2(ok2, q.x, a2[2*v]);
            a2[2*v+1] = fma2(ok2, q.y, a2[2*v+1]);
        }
    }
    #pragma unroll
    for (int m = 0; m < 5; ++m) {
        const float om = obs_out[m];
        const u64 om2 = pack2(om, om);
        const ulonglong2* w2 = (const ulonglong2*)&sm[S_WFC1 + (85 + m) * 64];
        #pragma unroll
        for (int v = 0; v < 16; ++v) {
            ulonglong2 q = w2[v];
            a2[2*v]   = fma2(om2, q.x, a2[2*v]);
            a2[2*v+1] = fma2(om2, q.y, a2[2*v+1]);
        }
    }

    __syncthreads();   // obs reads done -> reuse region as per-row scratch
    float* scr = &sm[S_OBS + tid * 65];   // stride 65: conflict-free dynamic access
    #pragma unroll
    for (int k = 0; k < 64; ++k) scr[k] = hi_[k];

    // pack xh[k] = {relu(x[k]), hi[k]}
    u64 xh[64];
    #pragma unroll
    for (int p = 0; p < 32; ++p) {
        float xl, xr;
        unpack2(a2[p], xl, xr);
        xh[2*p]   = pack2(fmaxf(xl, 0.f), hi_[2*p]);
        xh[2*p+1] = pack2(fmaxf(xr, 0.f), hi_[2*p+1]);
    }

    // ---------------- stage 4: GRU in f32x2 ----------------
    float hq0 = sm[S_BFC2], hq1 = sm[S_BFC2 + 1], hq2 = sm[S_BFC2 + 2];
    float hq3 = sm[S_BFC2 + 3], hq4 = sm[S_BFC2 + 4];

    #pragma unroll 1
    for (int j = 0; j < 64; ++j) {
        const float4 gb = *(const float4*)&sm[S_GB + 4 * j];   // {br, bz, bni, bnh}
        const ulonglong2* wr2 = (const ulonglong2*)&sm[S_WG + (j        ) * 128];
        const ulonglong2* wz2 = (const ulonglong2*)&sm[S_WG + (64 + j   ) * 128];
        const ulonglong2* wn2 = (const ulonglong2*)&sm[S_WG + (128 + j  ) * 128];

        // gate r: acc pairs are {x-part, h-part}
        u64 c0 = pack2(gb.x, 0.f), c1 = 0ull, c2 = 0ull, c3 = 0ull;
        #pragma unroll
        for (int kk = 0; kk < 32; kk += 2) {
            ulonglong2 wA = wr2[kk], wB = wr2[kk + 1];
            c0 = fma2(xh[2*kk],     wA.x, c0);
            c1 = fma2(xh[2*kk + 1], wA.y, c1);
            c2 = fma2(xh[2*kk + 2], wB.x, c2);
            c3 = fma2(xh[2*kk + 3], wB.y, c3);
        }
        float rx, rh;
        unpack2(add2(add2(c0, c1), add2(c2, c3)), rx, rh);
        const float r_ = fsig(rx + rh);

        // gate z
        c0 = pack2(gb.y, 0.f); c1 = 0ull; c2 = 0ull; c3 = 0ull;
        #pragma unroll
        for (int kk = 0; kk < 32; kk += 2) {
            ulonglong2 wA = wz2[kk], wB = wz2[kk + 1];
            c0 = fma2(xh[2*kk],     wA.x, c0);
            c1 = fma2(xh[2*kk + 1], wA.y, c1);
            c2 = fma2(xh[2*kk + 2], wB.x, c2);
            c3 = fma2(xh[2*kk + 3], wB.y, c3);
        }
        float zx, zh;
        unpack2(add2(add2(c0, c1), add2(c2, c3)), zx, zh);
        const float z_ = fsig(zx + zh);

        // gate n (keep x/h parts separate)
        c0 = pack2(gb.z, gb.w); c1 = 0ull; c2 = 0ull; c3 = 0ull;
        #pragma unroll
        for (int kk = 0; kk < 32; kk += 2) {
            ulonglong2 wA = wn2[kk], wB = wn2[kk + 1];
            c0 = fma2(xh[2*kk],     wA.x, c0);
            c1 = fma2(xh[2*kk + 1], wA.y, c1);
            c2 = fma2(xh[2*kk + 2], wB.x, c2);
            c3 = fma2(xh[2*kk + 3], wB.y, c3);
        }
        float nx, nh;
        unpack2(add2(add2(c0, c1), add2(c2, c3)), nx, nh);
        const float n_ = ftanh(fmaf(r_, nh, nx));

        const float hj = scr[j];                  // h_in[j] (dynamic, conflict-free)
        const float h_ = n_ + z_ * (hj - n_);
        scr[j] = h_;
        hq0 = fmaf(h_, sm[S_WFC2 + j * 5],     hq0);
        hq1 = fmaf(h_, sm[S_WFC2 + j * 5 + 1], hq1);
        hq2 = fmaf(h_, sm[S_WFC2 + j * 5 + 2], hq2);
        hq3 = fmaf(h_, sm[S_WFC2 + j * 5 + 3], hq3);
        hq4 = fmaf(h_, sm[S_WFC2 + j * 5 + 4], hq4);
    }

    // ---------------- stores ----------------
    {
        float* qp = out_q + (size_t)row * 5;
        qp[0] = hq0; qp[1] = hq1; qp[2] = hq2; qp[3] = hq3; qp[4] = hq4;

        float4* ho4 = (float4*)(out_h + (size_t)row * 64);
        #pragma unroll 1
        for (int i = 0; i < 16; ++i) {
            float4 v;
            v.x = scr[4*i]; v.y = scr[4*i+1]; v.z = scr[4*i+2]; v.w = scr[4*i+3];
            ho4[i] = v;
        }
    }
}

extern "C" void kernel_launch(void* const* d_in, const int* in_sizes, int n_in,
                              void* d_out, int out_size)
{
    const float* g_obs  = (const float*)d_in[0];
    const float* g_hid  = (const float*)d_in[1];
    const float* w_in0  = (const float*)d_in[2];
    const float* b_in0  = (const float*)d_in[3];
    const float* w_in1  = (const float*)d_in[4];
    const float* b_in1  = (const float*)d_in[5];
    const float* w_in2  = (const float*)d_in[6];
    const float* b_in2  = (const float*)d_in[7];
    const float* g_W    = (const float*)d_in[8];
    const float* g_a    = (const float*)d_in[9];
    const float* w_o1   = (const float*)d_in[10];
    const float* b_o1   = (const float*)d_in[11];
    const float* w_o2   = (const float*)d_in[12];
    const float* b_o2   = (const float*)d_in[13];
    const float* w_o3   = (const float*)d_in[14];
    const float* b_o3   = (const float*)d_in[15];
    const float* w_fc1  = (const float*)d_in[16];
    const float* b_fc1  = (const float*)d_in[17];
    const float* w_ih   = (const float*)d_in[18];
    const float* w_hh   = (const float*)d_in[19];
    const float* b_ih   = (const float*)d_in[20];
    const float* b_hh   = (const float*)d_in[21];
    const float* w_fc2  = (const float*)d_in[22];
    const float* b_fc2  = (const float*)d_in[23];

    float* out   = (float*)d_out;
    float* out_q = out;                          // q: (65536, 5)
    float* out_h = out + (size_t)65536 * 5;      // h: (65536, 64)

    const int smem_bytes = S_TOT * 4;            // 222000 B
    cudaFuncSetAttribute(atom_rnn_kernel,
                         cudaFuncAttributeMaxDynamicSharedMemorySize, smem_bytes);

    atom_rnn_kernel<<<NBLK, NB, smem_bytes>>>(
        g_obs, g_hid, w_in0, b_in0, w_in1, b_in1, w_in2, b_in2, g_W, g_a,
        w_o1, b_o1, w_o2, b_o2, w_o3, b_o3, w_fc1, b_fc1,
        w_ih, w_hh, b_ih, b_hh, w_fc2, b_fc2, out_q, out_h);
}

// round 6
// speedup vs baseline: 1.3715x; 1.3715x over previous
#include <cuda_runtime.h>

#define ALPHA 0.01f

// ---------------- global scratch for x = relu(fc1) ----------------
__device__ float g_xscr[65536 * 64];   // 16 MB static device scratch

__device__ __forceinline__ float lrelu(float v) { return fmaxf(v, ALPHA * v); }
__device__ __forceinline__ float fsig(float v)  { return __fdividef(1.0f, 1.0f + __expf(-v)); }
__device__ __forceinline__ float ftanh(float v) { return 1.0f - __fdividef(2.0f, __expf(2.0f * v) + 1.0f); }

// ================= Kernel A: tokens -> attention -> fc1 =================
#define NBA    256
#define ROWSA  128
// smem layout (float offsets)
#define A_WIN   0        // 1536
#define A_BIN   1536     // 192
#define A_WA1   1728     // 64
#define A_WA2   1792     // 64
#define A_WO1   1856     // 320
#define A_BO1   2176     // 32
#define A_WO2   2208     // 512
#define A_BO2   2720     // 16
#define A_WO3   2736     // 16
#define A_BO3   2752     // 1 (+3)
#define A_WFC1  2756     // 5760
#define A_BFC1  8516     // 64
#define A_OBS   8580     // 128*85 = 10880
#define A_WHX   19460    // 128*21 = 2688 (wh exchange, odd stride)
#define A_HPV   22148    // 128*5  = 640
#define A_TOT   22788    // floats = 91152 bytes

__global__ void __launch_bounds__(NBA, 2)
stageA_kernel(const float* __restrict__ g_obs,
              const float* __restrict__ w_in0, const float* __restrict__ b_in0,
              const float* __restrict__ w_in1, const float* __restrict__ b_in1,
              const float* __restrict__ w_in2, const float* __restrict__ b_in2,
              const float* __restrict__ g_W,  const float* __restrict__ g_a,
              const float* __restrict__ w_o1, const float* __restrict__ b_o1,
              const float* __restrict__ w_o2, const float* __restrict__ b_o2,
              const float* __restrict__ w_o3, const float* __restrict__ b_o3,
              const float* __restrict__ w_fc1, const float* __restrict__ b_fc1)
{
    extern __shared__ float sm[];
    const int tid  = threadIdx.x;
    const int lrow = tid & 127;
    const int half = tid >> 7;            // warp-uniform (warps 0-3 / 4-7)
    const int row  = blockIdx.x * ROWSA + lrow;

    #define CPY4(off, src, n) { const float4* s4_ = (const float4*)(src); \
                                float4* d4_ = (float4*)&sm[off]; \
                                for (int i = tid; i < (n)/4; i += NBA) d4_[i] = s4_[i]; }
    CPY4(A_WIN,        w_in0, 512);
    CPY4(A_WIN + 512,  w_in1, 512);
    CPY4(A_WIN + 1024, w_in2, 512);
    CPY4(A_BIN,        b_in0, 64);
    CPY4(A_BIN + 64,   b_in1, 64);
    CPY4(A_BIN + 128,  b_in2, 64);
    CPY4(A_WO1, w_o1, 320);  CPY4(A_BO1, b_o1, 32);
    CPY4(A_WO2, w_o2, 512);  CPY4(A_BO2, b_o2, 16);
    CPY4(A_WO3, w_o3, 16);
    CPY4(A_WFC1, w_fc1, 5760); CPY4(A_BFC1, b_fc1, 64);
    #undef CPY4
    if (tid == 0) sm[A_BO3] = b_o3[0];

    // Wa1 = W @ a[:64], Wa2 = W @ a[64:]
    if (tid < 128) {
        const int j = tid & 63;
        const float* av = g_a + ((tid < 64) ? 0 : 64);
        const float* wr = g_W + j * 64;
        float s = 0.f;
        #pragma unroll 8
        for (int m = 0; m < 64; ++m) s = fmaf(wr[m], av[m], s);
        sm[((tid < 64) ? A_WA1 : A_WA2) + j] = s;
    }

    // stage obs tile
    {
        const float4* src4 = (const float4*)(g_obs + (size_t)blockIdx.x * ROWSA * 85);
        float4* dst4 = (float4*)&sm[A_OBS];
        for (int i = tid; i < ROWSA * 85 / 4; i += NBA) dst4[i] = src4[i];
    }
    __syncthreads();

    const float* orow = &sm[A_OBS + lrow * 85];

    // ---------------- stage 1: 5 tokens per half ----------------
    #pragma unroll
    for (int tt = 0; tt < 5; ++tt) {
        const int sel = half ? ((tt < 4) ? 1 : 2) : 0;
        float o[8];
        #pragma unroll
        for (int f = 0; f < 8; ++f) {
            int idx = half * 40 + tt * 8 + 4 + f;       // (t*8+f+4) % 80
            if (idx >= 80) idx -= 80;
            o[f] = orow[idx];
        }
        const float4* w4   = (const float4*)&sm[A_WIN + sel * 512];
        const float4* b4   = (const float4*)&sm[A_BIN + sel * 64];
        const float4* wa14 = (const float4*)&sm[A_WA1];
        const float4* wa24 = (const float4*)&sm[A_WA2];
        float s1 = 0.f, s2 = 0.f;
        #pragma unroll 4
        for (int jv = 0; jv < 16; ++jv) {
            float4 acc = b4[jv];
            #pragma unroll
            for (int f = 0; f < 8; ++f) {
                float4 wv = w4[f * 16 + jv];
                acc.x = fmaf(o[f], wv.x, acc.x);
                acc.y = fmaf(o[f], wv.y, acc.y);
                acc.z = fmaf(o[f], wv.z, acc.z);
                acc.w = fmaf(o[f], wv.w, acc.w);
            }
            acc.x = lrelu(acc.x); acc.y = lrelu(acc.y);
            acc.z = lrelu(acc.z); acc.w = lrelu(acc.w);
            float4 a1 = wa14[jv], a2 = wa24[jv];
            s1 = fmaf(acc.x, a1.x, s1); s1 = fmaf(acc.y, a1.y, s1);
            s1 = fmaf(acc.z, a1.z, s1); s1 = fmaf(acc.w, a1.w, s1);
            s2 = fmaf(acc.x, a2.x, s2); s2 = fmaf(acc.y, a2.y, s2);
            s2 = fmaf(acc.z, a2.z, s2); s2 = fmaf(acc.w, a2.w, s2);
        }
        const int t = half * 5 + tt;
        sm[A_WHX + lrow * 21 + 2 * t]     = s1;
        sm[A_WHX + lrow * 21 + 2 * t + 1] = s2;
    }
    __syncthreads();

    float wh1[10], wh2[10];
    #pragma unroll
    for (int t = 0; t < 10; ++t) {
        wh1[t] = sm[A_WHX + lrow * 21 + 2 * t];
        wh2[t] = sm[A_WHX + lrow * 21 + 2 * t + 1];
    }

    // ---------------- stage 2: attention rows (3 / 2 per half) ----------------
    float mx1[5], dinv1[5];
    #pragma unroll
    for (int c = 0; c < 5; ++c) {
        float mx = -1e30f;
        #pragma unroll
        for (int r2 = 0; r2 < 5; ++r2) mx = fmaxf(mx, lrelu(wh1[5 + c] + wh2[r2]));
        float d = 0.f;
        #pragma unroll
        for (int r2 = 0; r2 < 5; ++r2) d += __expf(lrelu(wh1[5 + c] + wh2[r2]) - mx);
        mx1[c] = mx; dinv1[c] = __fdividef(1.0f, d);
    }

    #pragma unroll
    for (int rr = 0; rr < 3; ++rr) {
        if (half && rr == 2) break;
        const int r = half ? (3 + rr) : rr;
        const float w1r = half ? wh1[3 + rr] : wh1[rr];
        const float w2r = half ? wh2[3 + rr] : wh2[rr];
        float att[10];
        {
            float ev[5]; float mx = -1e30f;
            #pragma unroll
            for (int c = 0; c < 5; ++c) {
                float v = lrelu(w1r + wh2[5 + c]);
                ev[c] = v; mx = fmaxf(mx, v);
            }
            float d = 0.f;
            #pragma unroll
            for (int c = 0; c < 5; ++c) { float e_ = __expf(ev[c] - mx); att[c] = e_; d += e_; }
            float inv = __fdividef(1.0f, d);
            #pragma unroll
            for (int c = 0; c < 5; ++c) att[c] *= inv;
            #pragma unroll
            for (int c = 0; c < 5; ++c)
                att[5 + c] = __expf(lrelu(wh1[5 + c] + w2r) - mx1[c]) * dinv1[c];
        }
        float h1[32];
        {
            const float4* wv4 = (const float4*)&sm[A_WO1];
            const float4* bv4 = (const float4*)&sm[A_BO1];
            #pragma unroll
            for (int jv = 0; jv < 8; ++jv) {
                float4 acc = bv4[jv];
                #pragma unroll
                for (int k = 0; k < 10; ++k) {
                    float4 wv = wv4[k * 8 + jv];
                    acc.x = fmaf(att[k], wv.x, acc.x);
                    acc.y = fmaf(att[k], wv.y, acc.y);
                    acc.z = fmaf(att[k], wv.z, acc.z);
                    acc.w = fmaf(att[k], wv.w, acc.w);
                }
                h1[4*jv]   = lrelu(acc.x); h1[4*jv+1] = lrelu(acc.y);
                h1[4*jv+2] = lrelu(acc.z); h1[4*jv+3] = lrelu(acc.w);
            }
        }
        float h2v[16];
        {
            const float4* wv4 = (const float4*)&sm[A_WO2];
            const float4* bv4 = (const float4*)&sm[A_BO2];
            #pragma unroll
            for (int jv = 0; jv < 4; ++jv) {
                float4 acc = bv4[jv];
                #pragma unroll
                for (int k = 0; k < 32; ++k) {
                    float4 wv = wv4[k * 4 + jv];
                    acc.x = fmaf(h1[k], wv.x, acc.x);
                    acc.y = fmaf(h1[k], wv.y, acc.y);
                    acc.z = fmaf(h1[k], wv.z, acc.z);
                    acc.w = fmaf(h1[k], wv.w, acc.w);
                }
                h2v[4*jv]   = lrelu(acc.x); h2v[4*jv+1] = lrelu(acc.y);
                h2v[4*jv+2] = lrelu(acc.z); h2v[4*jv+3] = lrelu(acc.w);
            }
        }
        float v = sm[A_BO3];
        {
            const float4* wv4 = (const float4*)&sm[A_WO3];
            #pragma unroll
            for (int kv = 0; kv < 4; ++kv) {
                float4 wv = wv4[kv];
                v = fmaf(h2v[4*kv],   wv.x, v);
                v = fmaf(h2v[4*kv+1], wv.y, v);
                v = fmaf(h2v[4*kv+2], wv.z, v);
                v = fmaf(h2v[4*kv+3], wv.w, v);
            }
        }
        sm[A_HPV + lrow * 5 + r] = lrelu(v);
    }
    __syncthreads();

    float obs_out[5];
    {
        float hp[5];
        #pragma unroll
        for (int r = 0; r < 5; ++r) hp[r] = sm[A_HPV + lrow * 5 + r];
        float mx = fmaxf(fmaxf(fmaxf(hp[0], hp[1]), fmaxf(hp[2], hp[3])), hp[4]);
        float d = 0.f;
        #pragma unroll
        for (int r = 0; r < 5; ++r) { obs_out[r] = __expf(hp[r] - mx); d += obs_out[r]; }
        float inv = __fdividef(1.0f, d);
        #pragma unroll
        for (int r = 0; r < 5; ++r) obs_out[r] *= inv;
    }

    // ---------------- stage 3: fc1 half (32 outputs) ----------------
    const int jbase = half * 32;
    float xacc[32];
    {
        const float4* bv4 = (const float4*)&sm[A_BFC1 + jbase];
        #pragma unroll
        for (int jv = 0; jv < 8; ++jv) {
            float4 b = bv4[jv];
            xacc[4*jv] = b.x; xacc[4*jv+1] = b.y; xacc[4*jv+2] = b.z; xacc[4*jv+3] = b.w;
        }
    }
    #pragma unroll 1
    for (int k = 0; k < 85; ++k) {
        const float ok = orow[k];
        const float4* wr4 = (const float4*)&sm[A_WFC1 + k * 64 + jbase];
        #pragma unroll
        for (int jv = 0; jv < 8; ++jv) {
            float4 wv = wr4[jv];
            xacc[4*jv]   = fmaf(ok, wv.x, xacc[4*jv]);
            xacc[4*jv+1] = fmaf(ok, wv.y, xacc[4*jv+1]);
            xacc[4*jv+2] = fmaf(ok, wv.z, xacc[4*jv+2]);
            xacc[4*jv+3] = fmaf(ok, wv.w, xacc[4*jv+3]);
        }
    }
    #pragma unroll
    for (int m = 0; m < 5; ++m) {
        const float om = obs_out[m];
        const float4* wr4 = (const float4*)&sm[A_WFC1 + (85 + m) * 64 + jbase];
        #pragma unroll
        for (int jv = 0; jv < 8; ++jv) {
            float4 wv = wr4[jv];
            xacc[4*jv]   = fmaf(om, wv.x, xacc[4*jv]);
            xacc[4*jv+1] = fmaf(om, wv.y, xacc[4*jv+1]);
            xacc[4*jv+2] = fmaf(om, wv.z, xacc[4*jv+2]);
            xacc[4*jv+3] = fmaf(om, wv.w, xacc[4*jv+3]);
        }
    }
    {
        float4* xo4 = (float4*)&g_xscr[(size_t)row * 64 + jbase];
        #pragma unroll
        for (int jv = 0; jv < 8; ++jv)
            xo4[jv] = make_float4(fmaxf(xacc[4*jv], 0.f),   fmaxf(xacc[4*jv+1], 0.f),
                                  fmaxf(xacc[4*jv+2], 0.f), fmaxf(xacc[4*jv+3], 0.f));
    }
}

// ================= Kernel B: GRU + q =================
#define NBB    512
#define ROWSB  256
#define XS     66        // x-tile stride (even for float2 align; degree-2 conflict)
// smem layout (float offsets)
#define B_WG    0        // interleaved {w_ih, w_hh}: 24576
#define B_GB    24576    // 64*4 bias quads
#define B_WFC2  24832    // 320
#define B_BFC2  25152    // 5 (+3)
#define B_XT    25160    // 256*66 = 16896
#define B_QP    42056    // 256*5 = 1280
#define B_TOT   43336    // floats = 173344 bytes

__global__ void __launch_bounds__(NBB, 1)
stageB_kernel(const float* __restrict__ g_hid,
              const float* __restrict__ w_ih, const float* __restrict__ w_hh,
              const float* __restrict__ b_ih, const float* __restrict__ b_hh,
              const float* __restrict__ w_fc2, const float* __restrict__ b_fc2,
              float* __restrict__ out_q, float* __restrict__ out_h)
{
    extern __shared__ float sm[];
    const int tid  = threadIdx.x;
    const int lrow = tid & 255;
    const int half = tid >> 8;            // warp-uniform (warps 0-7 / 8-15)
    const int row  = blockIdx.x * ROWSB + lrow;
    const int jbase = half * 32;

    // stage GRU weights interleaved: sm[B_WG + 2i] = w_ih[i], +1 = w_hh[i]
    for (int i = tid; i < 12288; i += NBB) {
        sm[B_WG + 2*i]     = w_ih[i];
        sm[B_WG + 2*i + 1] = w_hh[i];
    }
    if (tid < 64) {
        const int j = tid;
        sm[B_GB + 4*j]     = b_ih[j]       + b_hh[j];
        sm[B_GB + 4*j + 1] = b_ih[64 + j]  + b_hh[64 + j];
        sm[B_GB + 4*j + 2] = b_ih[128 + j];
        sm[B_GB + 4*j + 3] = b_hh[128 + j];
    }
    for (int i = tid; i < 320; i += NBB) sm[B_WFC2 + i] = w_fc2[i];
    if (tid >= 64 && tid < 69) sm[B_BFC2 + tid - 64] = b_fc2[tid - 64];

    // stage x tile (coalesced global reads)
    {
        const float* src = &g_xscr[(size_t)blockIdx.x * ROWSB * 64];
        for (int i = tid; i < ROWSB * 64; i += NBB) {
            const int r = i >> 6, k = i & 63;
            sm[B_XT + r * XS + k] = src[i];
        }
    }

    // load h_in into registers (only big per-thread array)
    const float* hid_row = g_hid + (size_t)row * 64;
    float hi[64];
    {
        const float4* hp4 = (const float4*)hid_row;
        #pragma unroll
        for (int i = 0; i < 16; ++i) {
            float4 v = hp4[i];
            hi[4*i] = v.x; hi[4*i+1] = v.y; hi[4*i+2] = v.z; hi[4*i+3] = v.w;
        }
    }
    __syncthreads();

    const float* xrow = &sm[B_XT + lrow * XS];
    float hq0 = 0.f, hq1 = 0.f, hq2 = 0.f, hq3 = 0.f, hq4 = 0.f;
    if (!half) {
        hq0 = sm[B_BFC2];     hq1 = sm[B_BFC2 + 1]; hq2 = sm[B_BFC2 + 2];
        hq3 = sm[B_BFC2 + 3]; hq4 = sm[B_BFC2 + 4];
    }
    float* hrow = out_h + (size_t)row * 64;

    #pragma unroll 1
    for (int jj = 0; jj < 32; ++jj) {
        const int j = jbase + jj;
        const float4 gb = *(const float4*)&sm[B_GB + 4 * j];   // {br, bz, bni, bnh}
        const float4* wr4 = (const float4*)&sm[B_WG + (j        ) * 128];
        const float4* wz4 = (const float4*)&sm[B_WG + (64 + j  ) * 128];
        const float4* wn4 = (const float4*)&sm[B_WG + (128 + j ) * 128];
        float axr = gb.x, ahr = 0.f;
        float axz = gb.y, ahz = 0.f;
        float axn = gb.z, ahn = gb.w;
        #pragma unroll
        for (int kk = 0; kk < 32; ++kk) {           // 2 k per iter
            const float2 xv = *(const float2*)&xrow[2 * kk];
            const float4 qr = wr4[kk];              // {wi_k, wh_k, wi_k1, wh_k1}
            const float4 qz = wz4[kk];
            const float4 qn = wn4[kk];
            const float h0 = hi[2*kk], h1v = hi[2*kk + 1];
            axr = fmaf(xv.x, qr.x, axr); ahr = fmaf(h0,  qr.y, ahr);
            axr = fmaf(xv.y, qr.z, axr); ahr = fmaf(h1v, qr.w, ahr);
            axz = fmaf(xv.x, qz.x, axz); ahz = fmaf(h0,  qz.y, ahz);
            axz = fmaf(xv.y, qz.z, axz); ahz = fmaf(h1v, qz.w, ahz);
            axn = fmaf(xv.x, qn.x, axn); ahn = fmaf(h0,  qn.y, ahn);
            axn = fmaf(xv.y, qn.z, axn); ahn = fmaf(h1v, qn.w, ahn);
        }
        const float r_ = fsig(axr + ahr);
        const float z_ = fsig(axz + ahz);
        const float n_ = ftanh(fmaf(r_, ahn, axn));
        const float hj = __ldg(hid_row + j);        // h_in[j] (L1/L2 hit)
        const float h_ = n_ + z_ * (hj - n_);
        hrow[j] = h_;                               // L2 write-combines across j
        hq0 = fmaf(h_, sm[B_WFC2 + j * 5],     hq0);
        hq1 = fmaf(h_, sm[B_WFC2 + j * 5 + 1], hq1);
        hq2 = fmaf(h_, sm[B_WFC2 + j * 5 + 2], hq2);
        hq3 = fmaf(h_, sm[B_WFC2 + j * 5 + 3], hq3);
        hq4 = fmaf(h_, sm[B_WFC2 + j * 5 + 4], hq4);
    }

    // combine q halves via smem
    if (half) {
        sm[B_QP + lrow * 5]     = hq0;
        sm[B_QP + lrow * 5 + 1] = hq1;
        sm[B_QP + lrow * 5 + 2] = hq2;
        sm[B_QP + lrow * 5 + 3] = hq3;
        sm[B_QP + lrow * 5 + 4] = hq4;
    }
    __syncthreads();
    if (!half) {
        float* qp = out_q + (size_t)row * 5;
        qp[0] = hq0 + sm[B_QP + lrow * 5];
        qp[1] = hq1 + sm[B_QP + lrow * 5 + 1];
        qp[2] = hq2 + sm[B_QP + lrow * 5 + 2];
        qp[3] = hq3 + sm[B_QP + lrow * 5 + 3];
        qp[4] = hq4 + sm[B_QP + lrow * 5 + 4];
    }
}

extern "C" void kernel_launch(void* const* d_in, const int* in_sizes, int n_in,
                              void* d_out, int out_size)
{
    const float* g_obs  = (const float*)d_in[0];
    const float* g_hid  = (const float*)d_in[1];
    const float* w_in0  = (const float*)d_in[2];
    const float* b_in0  = (const float*)d_in[3];
    const float* w_in1  = (const float*)d_in[4];
    const float* b_in1  = (const float*)d_in[5];
    const float* w_in2  = (const float*)d_in[6];
    const float* b_in2  = (const float*)d_in[7];
    const float* g_W    = (const float*)d_in[8];
    const float* g_a    = (const float*)d_in[9];
    const float* w_o1   = (const float*)d_in[10];
    const float* b_o1   = (const float*)d_in[11];
    const float* w_o2   = (const float*)d_in[12];
    const float* b_o2   = (const float*)d_in[13];
    const float* w_o3   = (const float*)d_in[14];
    const float* b_o3   = (const float*)d_in[15];
    const float* w_fc1  = (const float*)d_in[16];
    const float* b_fc1  = (const float*)d_in[17];
    const float* w_ih   = (const float*)d_in[18];
    const float* w_hh   = (const float*)d_in[19];
    const float* b_ih   = (const float*)d_in[20];
    const float* b_hh   = (const float*)d_in[21];
    const float* w_fc2  = (const float*)d_in[22];
    const float* b_fc2  = (const float*)d_in[23];

    float* out   = (float*)d_out;
    float* out_q = out;                          // q: (65536, 5)
    float* out_h = out + (size_t)65536 * 5;      // h: (65536, 64)

    const int smemA = A_TOT * 4;                 // 91152 B (2 blocks/SM)
    const int smemB = B_TOT * 4;                 // 173344 B
    cudaFuncSetAttribute(stageA_kernel, cudaFuncAttributeMaxDynamicSharedMemorySize, smemA);
    cudaFuncSetAttribute(stageB_kernel, cudaFuncAttributeMaxDynamicSharedMemorySize, smemB);

    stageA_kernel<<<65536 / ROWSA, NBA, smemA>>>(
        g_obs, w_in0, b_in0, w_in1, b_in1, w_in2, b_in2, g_W, g_a,
        w_o1, b_o1, w_o2, b_o2, w_o3, b_o3, w_fc1, b_fc1);

    stageB_kernel<<<65536 / ROWSB, NBB, smemB>>>(
        g_hid, w_ih, w_hh, b_ih, b_hh, w_fc2, b_fc2, out_q, out_h);
}